// round 10
// baseline (speedup 1.0000x reference)
#include <cuda_runtime.h>
#include <math.h>

#define BB 32
#define SS 256
#define EE 300
#define EP 304
#define HH 256
#define T4H 1024
#define NT 19
#define TSTART 17
#define TSTOP 18
#define NHS 16   // hidden slices (16 units each)
#define NBS 4    // batch slices (8 batches each)

typedef unsigned long long ull;

__device__ __forceinline__ ull fma2(ull a, ull b, ull c) {
    ull d;
    asm("fma.rn.f32x2 %0, %1, %2, %3;" : "=l"(d) : "l"(a), "l"(b), "l"(c));
    return d;
}
__device__ __forceinline__ ull pack2(float lo, float hi) {
    ull r;
    asm("mov.b64 %0, {%1, %2};" : "=l"(r) : "f"(lo), "f"(hi));
    return r;
}
__device__ __forceinline__ float fsigmoid(float x) {
    return 1.0f / (1.0f + __expf(-x));
}
__device__ __forceinline__ float ftanh_fast(float x) {
    return 1.0f - 2.0f / (__expf(2.0f * x) + 1.0f);
}

// ---------------- device scratch (no cudaMalloc allowed) ----------------
__device__ float    g_X[(size_t)BB * SS * EP];            // [n][e], n = t*32 + b
__device__ float    g_xg[(size_t)2 * SS * T4H * BB];      // [d][t][row][b]
__device__ float    g_h2[(size_t)2 * SS * NBS * 2048];    // [d][t][bs][k][8b]
__device__ float    g_logits[(size_t)BB * SS * NT];       // [b][t][tag]
__device__ int      g_ptr[(size_t)BB * SS * NT];          // viterbi backpointers
__device__ float    g_nll[BB];
__device__ unsigned g_flag[2 * NBS * NHS];                // [d][bs][hs] monotonic step counters

// ---------------- zero output + flags ----------------
__global__ void zero_out_kernel(float* out, int n) {
    int i = blockIdx.x * blockDim.x + threadIdx.x;
    if (i < n) out[i] = 0.0f;
    if (i < 2 * NBS * NHS) g_flag[i] = 0u;
}

// ---------------- embedding gather + mask -> padded X [8192][304] ----------------
__global__ void embed_kernel(const int* __restrict__ word, const int* __restrict__ mask,
                             const float* __restrict__ emb) {
    int idx = blockIdx.x * blockDim.x + threadIdx.x;
    int total = BB * SS * (EP / 4);
    if (idx >= total) return;
    int n = idx / (EP / 4), q = idx - n * (EP / 4);
    int t = n >> 5, b = n & 31;
    int w = word[b * SS + t];
    float m = (float)mask[b * SS + t];
    int e = q * 4;
    float4 v;
    if (e < EE) {
        float4 ev = *(const float4*)(emb + (size_t)w * EE + e);
        v.x = ev.x * m; v.y = ev.y * m; v.z = ev.z * m; v.w = ev.w * m;
    } else {
        v.x = v.y = v.z = v.w = 0.0f;
    }
    ((float4*)g_X)[(size_t)n * (EP / 4) + q] = v;
}

// ---------------- input-transform GEMM (f32x2): xg = X @ Wih_d.T + bih + bhh ----------------
__global__ __launch_bounds__(256) void gemm_xg_kernel(
    const float* __restrict__ WihF, const float* __restrict__ WihB,
    const float* __restrict__ bihF, const float* __restrict__ bhhF,
    const float* __restrict__ bihB, const float* __restrict__ bhhB) {
    __shared__ ull   As[16][64];
    __shared__ float Xs[16][68];
    int d = blockIdx.z;
    const float* Wih = d ? WihB : WihF;
    const float* bih = d ? bihB : bihF;
    const float* bhh = d ? bhhB : bhhF;
    int m0 = blockIdx.y * 64, n0 = blockIdx.x * 64;
    int tid = threadIdx.x;
    int lm = tid >> 2, kq = (tid & 3) * 4;
    int tx = tid & 15, ty = tid >> 4;
    ull acc[4][2];
#pragma unroll
    for (int i = 0; i < 4; i++) { acc[i][0] = 0ULL; acc[i][1] = 0ULL; }

    for (int e0 = 0; e0 < EP; e0 += 16) {
        float4 a;
        if (e0 + kq < EE) {
            a = *(const float4*)(Wih + (size_t)(m0 + lm) * EE + e0 + kq);
        } else {
            a.x = a.y = a.z = a.w = 0.0f;
        }
        As[kq + 0][lm] = pack2(a.x, a.x);
        As[kq + 1][lm] = pack2(a.y, a.y);
        As[kq + 2][lm] = pack2(a.z, a.z);
        As[kq + 3][lm] = pack2(a.w, a.w);
        float4 xv = *(const float4*)(g_X + (size_t)(n0 + lm) * EP + e0 + kq);
        Xs[kq + 0][lm] = xv.x; Xs[kq + 1][lm] = xv.y; Xs[kq + 2][lm] = xv.z; Xs[kq + 3][lm] = xv.w;
        __syncthreads();
#pragma unroll
        for (int k = 0; k < 16; k++) {
            ulonglong2 w01 = *(const ulonglong2*)&As[k][ty * 4];
            ulonglong2 w23 = *(const ulonglong2*)&As[k][ty * 4 + 2];
            ulonglong2 xx  = *(const ulonglong2*)&Xs[k][tx * 4];
            acc[0][0] = fma2(w01.x, xx.x, acc[0][0]); acc[0][1] = fma2(w01.x, xx.y, acc[0][1]);
            acc[1][0] = fma2(w01.y, xx.x, acc[1][0]); acc[1][1] = fma2(w01.y, xx.y, acc[1][1]);
            acc[2][0] = fma2(w23.x, xx.x, acc[2][0]); acc[2][1] = fma2(w23.x, xx.y, acc[2][1]);
            acc[3][0] = fma2(w23.y, xx.x, acc[3][0]); acc[3][1] = fma2(w23.y, xx.y, acc[3][1]);
        }
        __syncthreads();
    }
#pragma unroll
    for (int i = 0; i < 4; i++) {
        int row = m0 + ty * 4 + i;
        float bias = bih[row] + bhh[row];
        float2 f0 = *(float2*)&acc[i][0];
        float2 f1 = *(float2*)&acc[i][1];
        float vals[4] = {f0.x, f0.y, f1.x, f1.y};
#pragma unroll
        for (int j = 0; j < 4; j++) {
            int n = n0 + tx * 4 + j;
            int tt = n >> 5, bb2 = n & 31;
            g_xg[(((size_t)d * SS + tt) * T4H + row) * BB + bb2] = vals[j] + bias;
        }
    }
}

// ---------------- persistent BiLSTM: 2D (hidden x batch) partitioning, L2 flags ----------------
// 128 blocks x 128 threads: bid = d*64 + bs*16 + hs.
// Block owns units [16hs,16hs+16) x batches [8bs,8bs+8): 64 gate rows x 8 batches.
// Gangs of 16 blocks (same d,bs) communicate; one flag per block per step.
__global__ __launch_bounds__(128, 1) void lstm_kernel(
    const float* __restrict__ WhhF, const float* __restrict__ WhhB) {
    extern __shared__ ull sm8[];
    ull* W_pack = sm8;            // [256 k][32 rp] {w_r0,w_r1}   (8192 ull = 64KB)
    ull* h_dup  = sm8 + 8192;     // [256 k][8 b]  {h,h}          (2048 ull = 16KB)
    ull* part   = sm8 + 10240;    // [(kq*32+rp)*9 + b]           (1152 ull = 9KB)

    int tid = threadIdx.x, bid = blockIdx.x;
    int d = bid >> 6, bs = (bid >> 4) & 3, hs = bid & 15;
    const float* Whh = d ? WhhB : WhhF;

    // stage packed Whh slice: W_pack[k*32+rp] = {Whh[grow(2rp)][k], Whh[grow(2rp+1)][k]}
    for (int i = tid; i < 8192; i += 128) {
        int rp = i & 31, k = i >> 5;
        int lr0 = rp * 2, lr1 = rp * 2 + 1;
        int gr0 = (lr0 >> 4) * HH + hs * 16 + (lr0 & 15);
        int gr1 = (lr1 >> 4) * HH + hs * 16 + (lr1 & 15);
        W_pack[k * 32 + rp] = pack2(Whh[(size_t)gr0 * HH + k], Whh[(size_t)gr1 * HH + k]);
    }
    __syncthreads();

    int lane = tid & 31, kq = tid >> 5;
    int u = tid >> 3, b = tid & 7;           // cell mapping: unit offset, local batch
    float c_reg = 0.0f;
    unsigned* flagG = g_flag + (d * NBS + bs) * NHS;

    for (int it = 0; it < SS; it++) {
        int t = d ? (SS - 1 - it) : it;

        // prefetch xg (4 strided coalesced loads, issued before the wait)
        float xgv[4];
        const float* xgb = g_xg + ((size_t)(d * SS + t) * T4H) * BB + bs * 8 + b;
#pragma unroll
        for (int gg = 0; gg < 4; gg++)
            xgv[gg] = xgb[(size_t)(gg * HH + hs * 16 + u) * BB];

        if (it > 0) {
            // poll the gang's 16 flags (one coalesced 64B acquire load per iteration)
            {
                const unsigned* fp = flagG + (lane & 15);
                unsigned v;
                do {
                    asm volatile("ld.acquire.gpu.global.u32 %0, [%1];"
                                 : "=r"(v) : "l"(fp) : "memory");
                } while (__ballot_sync(0xffffffffu, v >= (unsigned)it) != 0xffffffffu);
            }

            // stage 8KB contiguous h slice, duplicating {h,h} into smem
            int tp = d ? t + 1 : t - 1;
            const float4* src4 = (const float4*)(g_h2 +
                (((size_t)(d * SS + tp)) * NBS + bs) * 2048);
            ulonglong2* hd2 = (ulonglong2*)h_dup;
#pragma unroll
            for (int j = 0; j < 4; j++) {
                int i4 = tid + j * 128;          // float4 index, 512 total
                float4 hv = src4[i4];
                ulonglong2 e0, e1;
                e0.x = pack2(hv.x, hv.x); e0.y = pack2(hv.y, hv.y);
                e1.x = pack2(hv.z, hv.z); e1.y = pack2(hv.w, hv.w);
                hd2[i4 * 2]     = e0;
                hd2[i4 * 2 + 1] = e1;
            }
            __syncthreads();

            // GEMV: warp kq covers k in [64kq,64kq+64); lane = row-pair; 8 batch accs
            ull a0 = 0ULL, a1 = 0ULL, a2 = 0ULL, a3 = 0ULL;
            ull a4 = 0ULL, a5 = 0ULL, a6 = 0ULL, a7 = 0ULL;
            int k0 = kq * 64;
#pragma unroll 4
            for (int k = k0; k < k0 + 64; k++) {
                ull wp = W_pack[k * 32 + lane];
                const ulonglong2* hr = (const ulonglong2*)&h_dup[k * 8];
                ulonglong2 h01 = hr[0], h23 = hr[1], h45 = hr[2], h67 = hr[3];
                a0 = fma2(wp, h01.x, a0); a1 = fma2(wp, h01.y, a1);
                a2 = fma2(wp, h23.x, a2); a3 = fma2(wp, h23.y, a3);
                a4 = fma2(wp, h45.x, a4); a5 = fma2(wp, h45.y, a5);
                a6 = fma2(wp, h67.x, a6); a7 = fma2(wp, h67.y, a7);
            }
            ull* pr = part + (size_t)(kq * 32 + lane) * 9;
            pr[0] = a0; pr[1] = a1; pr[2] = a2; pr[3] = a3;
            pr[4] = a4; pr[5] = a5; pr[6] = a6; pr[7] = a7;
        }
        __syncthreads();   // parts visible to cell phase (and h_dup reuse guarded)

        // cell update: thread -> (u, b)
        {
            const float* pf = (const float*)part;
            float g[4];
#pragma unroll
            for (int gg = 0; gg < 4; gg++) {
                float s = xgv[gg];
                if (it > 0) {
                    int lr = gg * 16 + u;
                    int rp = lr >> 1, hf = lr & 1;
#pragma unroll
                    for (int kk = 0; kk < 4; kk++)
                        s += pf[((size_t)(kk * 32 + rp) * 9 + b) * 2 + hf];
                }
                g[gg] = s;
            }
            float iv = fsigmoid(g[0]);
            float fv = fsigmoid(g[1]);
            float gv = ftanh_fast(g[2]);
            float ov = fsigmoid(g[3]);
            c_reg = fv * c_reg + iv * gv;
            float hval = ov * ftanh_fast(c_reg);
            // contiguous 512B block write: [d][t][bs][k=16hs+u][b]
            g_h2[(((size_t)(d * SS + t)) * NBS + bs) * 2048 + (hs * 16 + u) * 8 + b] = hval;
        }
        __syncthreads();   // all h writes done before publish; part consumed

        if (tid == 0) {
            unsigned* fp = flagG + hs;
            unsigned val = (unsigned)(it + 1);
            asm volatile("st.release.gpu.global.u32 [%0], %1;" :: "l"(fp), "r"(val) : "memory");
        }
        // producers never wait on consumers; g_h2 slots are per-t (no reuse hazard)
    }
}

// ---------------- logits: [b][t][tag] = hcat . W_tag[tag] + b_tag ----------------
__global__ __launch_bounds__(256) void logits_kernel(const float* __restrict__ Wtag,
                                                     const float* __restrict__ btag) {
    extern __shared__ float hb[];  // [512 k][32 b]
    int t = blockIdx.x;
    int tid = threadIdx.x;
    for (int dd = 0; dd < 2; dd++) {
        for (int bs = 0; bs < NBS; bs++) {
            const float4* src = (const float4*)(g_h2 +
                (((size_t)(dd * SS + t)) * NBS + bs) * 2048);
            for (int j = tid; j < 512; j += 256) {
                int k = j >> 1, b8 = (j & 1) * 4;
                *(float4*)&hb[(dd * 256 + k) * 32 + bs * 8 + b8] = src[j];
            }
        }
    }
    __syncthreads();
    for (int o = tid; o < BB * NT; o += 256) {
        int tag = o >> 5;
        int b = o & 31;
        float acc = btag[tag];
        const float* wr = Wtag + (size_t)tag * (2 * HH);
#pragma unroll 8
        for (int k = 0; k < 2 * HH; k++) acc += hb[k * BB + b] * wr[k];
        g_logits[((size_t)b * SS + t) * NT + tag] = acc;
    }
}

// ---------------- merged CRF forward + Viterbi (grid 32 x 2) ----------------
__global__ void crf_vit_kernel(const int* __restrict__ mask, const int* __restrict__ labels,
                               const float* __restrict__ trans, float* __restrict__ out) {
    __shared__ float tr[NT * NT];
    __shared__ float st[NT];
    int b = blockIdx.x, j = threadIdx.x;
    for (int i = j; i < NT * NT; i += 32) tr[i] = trans[i];
    __syncthreads();

    if (blockIdx.y == 0) {
        if (j < NT) st[j] = g_logits[((size_t)b * SS) * NT + j] + tr[TSTART * NT + j];
        __syncthreads();
        for (int t = 1; t < SS; t++) {
            int mt = mask[b * SS + t];
            float nv = 0.0f;
            if (j < NT) {
                float mx = -1e30f;
#pragma unroll
                for (int i = 0; i < NT; i++) mx = fmaxf(mx, st[i] + tr[i * NT + j]);
                float sum = 0.0f;
#pragma unroll
                for (int i = 0; i < NT; i++) sum += __expf(st[i] + tr[i * NT + j] - mx);
                nv = mx + __logf(sum) + g_logits[((size_t)b * SS + t) * NT + j];
            }
            __syncthreads();
            if (j < NT && mt > 0) st[j] = nv;
            __syncthreads();
        }
        if (j == 0) {
            float mx = -1e30f;
            for (int i = 0; i < NT; i++) mx = fmaxf(mx, st[i] + tr[i * NT + TSTOP]);
            float sum = 0.0f;
            for (int i = 0; i < NT; i++) sum += __expf(st[i] + tr[i * NT + TSTOP] - mx);
            float logZ = mx + __logf(sum);
            float gold = 0.0f;
            int prev = TSTART, len = 0;
            for (int t = 0; t < SS; t++) {
                int lab = labels[b * SS + t];
                if (mask[b * SS + t] > 0) {
                    gold += tr[prev * NT + lab] + g_logits[((size_t)b * SS + t) * NT + lab];
                    len++;
                }
                prev = lab;
            }
            int last = labels[b * SS + len - 1];
            gold += tr[last * NT + TSTOP];
            g_nll[b] = logZ - gold;
        }
    } else {
        if (j < NT) st[j] = g_logits[((size_t)b * SS) * NT + j] + tr[TSTART * NT + j];
        __syncthreads();
        for (int t = 1; t < SS; t++) {
            int mt = mask[b * SS + t];
            float nv = 0.0f;
            int arg = j;
            if (j < NT) {
                float best = -1e30f;
                int bi = 0;
#pragma unroll
                for (int i = 0; i < NT; i++) {
                    float v = st[i] + tr[i * NT + j];
                    if (v > best) { best = v; bi = i; }  // strict '>' => first max (jnp.argmax)
                }
                nv = best + g_logits[((size_t)b * SS + t) * NT + j];
                if (mt > 0) arg = bi;
            }
            __syncthreads();
            if (j < NT) {
                if (mt > 0) st[j] = nv;
                g_ptr[((size_t)b * SS + t) * NT + j] = arg;
            }
            __syncthreads();
        }
        if (j == 0) {
            float best = -1e30f;
            int bl = 0;
            for (int i = 0; i < NT; i++) {
                float v = st[i] + tr[i * NT + TSTOP];
                if (v > best) { best = v; bl = i; }
            }
            int tag = bl;
            for (int t = SS - 1; t >= 1; t--) {
                out[1 + b * SS + t] = (float)(mask[b * SS + t] > 0 ? tag : 0);
                tag = g_ptr[((size_t)b * SS + t) * NT + tag];
            }
            out[1 + b * SS + 0] = (float)(mask[b * SS + 0] > 0 ? tag : 0);
        }
    }
}

__global__ void finalize_kernel(float* out) {
    if (threadIdx.x == 0) {
        float s = 0.0f;
        for (int i = 0; i < BB; i++) s += g_nll[i];
        out[0] = s / (float)BB;
    }
}

extern "C" void kernel_launch(void* const* d_in, const int* in_sizes, int n_in,
                              void* d_out, int out_size) {
    int o = (in_sizes[4] == 1) ? 0 : -1;  // data_type scalar present or dropped
    const int*   word   = (const int*)d_in[0];
    const int*   mask   = (const int*)d_in[1];
    const int*   labels = (const int*)d_in[2];
    const float* emb    = (const float*)d_in[5 + o];
    const float* WihF   = (const float*)d_in[6 + o];
    const float* WhhF   = (const float*)d_in[7 + o];
    const float* bihF   = (const float*)d_in[8 + o];
    const float* bhhF   = (const float*)d_in[9 + o];
    const float* WihB   = (const float*)d_in[10 + o];
    const float* WhhB   = (const float*)d_in[11 + o];
    const float* bihB   = (const float*)d_in[12 + o];
    const float* bhhB   = (const float*)d_in[13 + o];
    const float* Wtag   = (const float*)d_in[14 + o];
    const float* btag   = (const float*)d_in[15 + o];
    const float* trans  = (const float*)d_in[16 + o];
    float* out = (float*)d_out;

    const int lstm_smem = (8192 + 2048 + 1152) * 8;  // 91136 B
    cudaFuncSetAttribute(lstm_kernel, cudaFuncAttributeMaxDynamicSharedMemorySize, lstm_smem);
    cudaFuncSetAttribute(logits_kernel, cudaFuncAttributeMaxDynamicSharedMemorySize, 65536);

    int nz = out_size > 2 * NBS * NHS ? out_size : 2 * NBS * NHS;
    zero_out_kernel<<<(nz + 255) / 256, 256>>>(out, out_size);
    embed_kernel<<<(BB * SS * (EP / 4) + 255) / 256, 256>>>(word, mask, emb);
    {
        dim3 grid(BB * SS / 64, T4H / 64, 2);
        gemm_xg_kernel<<<grid, 256>>>(WihF, WihB, bihF, bhhF, bihB, bhhB);
    }
    lstm_kernel<<<128, 128, lstm_smem>>>(WhhF, WhhB);
    logits_kernel<<<SS, 256, 65536>>>(Wtag, btag);
    crf_vit_kernel<<<dim3(BB, 2), 32>>>(mask, labels, trans, out);
    finalize_kernel<<<1, 32>>>(out);
}

// round 11
// speedup vs baseline: 1.7883x; 1.7883x over previous
#include <cuda_runtime.h>
#include <math.h>

#define BB 32
#define SS 256
#define EE 300
#define EP 304
#define HH 256
#define T4H 1024
#define NT 19
#define TSTART 17
#define TSTOP 18

typedef unsigned long long ull;

__device__ __forceinline__ ull fma2(ull a, ull b, ull c) {
    ull d;
    asm("fma.rn.f32x2 %0, %1, %2, %3;" : "=l"(d) : "l"(a), "l"(b), "l"(c));
    return d;
}
__device__ __forceinline__ ull pack2(float lo, float hi) {
    ull r;
    asm("mov.b64 %0, {%1, %2};" : "=l"(r) : "f"(lo), "f"(hi));
    return r;
}
__device__ __forceinline__ float fsigmoid(float x) {
    return 1.0f / (1.0f + __expf(-x));
}
__device__ __forceinline__ float ftanh_fast(float x) {
    return 1.0f - 2.0f / (__expf(2.0f * x) + 1.0f);
}

// ---------------- device scratch (no cudaMalloc allowed) ----------------
__device__ float    g_X[(size_t)BB * SS * EP];            // [n][e], n = t*32 + b
__device__ float    g_xg[(size_t)2 * SS * T4H * BB];      // [d][t][row][b]
__device__ float    g_h[(size_t)2 * SS * HH * BB];        // [d][t][k][b]
__device__ float    g_logits[(size_t)BB * SS * NT];       // [b][t][tag]
__device__ int      g_ptr[(size_t)BB * SS * NT];          // viterbi backpointers
__device__ unsigned g_bar[2 * SS * 4];                    // [dir][step][group] arrival counters

// ---------------- embedding gather + mask -> padded X; also inits out[0] + counters ----------------
__global__ void embed_kernel(const int* __restrict__ word, const int* __restrict__ mask,
                             const float* __restrict__ emb, float* __restrict__ out) {
    int idx = blockIdx.x * blockDim.x + threadIdx.x;
    if (idx == 0) out[0] = 0.0f;                 // crf blocks atomicAdd into this
    if (idx < 2 * SS * 4) g_bar[idx] = 0u;       // reset per-step barrier counters
    int total = BB * SS * (EP / 4);
    if (idx >= total) return;
    int n = idx / (EP / 4), q = idx - n * (EP / 4);
    int t = n >> 5, b = n & 31;
    int w = word[b * SS + t];
    float m = (float)mask[b * SS + t];
    int e = q * 4;
    float4 v;
    if (e < EE) {
        float4 ev = *(const float4*)(emb + (size_t)w * EE + e);
        v.x = ev.x * m; v.y = ev.y * m; v.z = ev.z * m; v.w = ev.w * m;
    } else {
        v.x = v.y = v.z = v.w = 0.0f;
    }
    ((float4*)g_X)[(size_t)n * (EP / 4) + q] = v;
}

// ---------------- input-transform GEMM (f32x2, 64x128 tiles): xg = X @ Wih_d.T + bih + bhh ----------------
// thread tile = 4 rows x 8 tokens (4 token-pair ulls) -> 16 FFMA2 : 4 LDS.128 per k
__global__ __launch_bounds__(256) void gemm_xg_kernel(
    const float* __restrict__ WihF, const float* __restrict__ WihB,
    const float* __restrict__ bihF, const float* __restrict__ bhhF,
    const float* __restrict__ bihB, const float* __restrict__ bhhB) {
    __shared__ ull   As[16][64];     // [k][row] duplicated {w,w}  (8KB)
    __shared__ float Xs[16][132];    // [k][token], pitch 132 (16B-aligned rows)
    int d = blockIdx.z;
    const float* Wih = d ? WihB : WihF;
    const float* bih = d ? bihB : bihF;
    const float* bhh = d ? bhhB : bhhF;
    int m0 = blockIdx.y * 64, n0 = blockIdx.x * 128;
    int tid = threadIdx.x;
    int lmA = tid >> 2, kqA = (tid & 3) * 4;   // W staging
    int tok = tid >> 1, f4b = (tid & 1) * 2;   // X staging (2 float4 per thread)
    int tx = tid & 15, ty = tid >> 4;          // compute: tokens tx*8.., rows ty*4..
    ull acc[4][4];
#pragma unroll
    for (int i = 0; i < 4; i++)
#pragma unroll
        for (int j = 0; j < 4; j++) acc[i][j] = 0ULL;

    for (int e0 = 0; e0 < EP; e0 += 16) {
        float4 a;
        if (e0 + kqA < EE) {
            a = *(const float4*)(Wih + (size_t)(m0 + lmA) * EE + e0 + kqA);
        } else {
            a.x = a.y = a.z = a.w = 0.0f;
        }
        As[kqA + 0][lmA] = pack2(a.x, a.x);
        As[kqA + 1][lmA] = pack2(a.y, a.y);
        As[kqA + 2][lmA] = pack2(a.z, a.z);
        As[kqA + 3][lmA] = pack2(a.w, a.w);
#pragma unroll
        for (int q = 0; q < 2; q++) {
            int f4 = f4b + q;
            float4 xv = *(const float4*)(g_X + (size_t)(n0 + tok) * EP + e0 + f4 * 4);
            Xs[f4 * 4 + 0][tok] = xv.x;
            Xs[f4 * 4 + 1][tok] = xv.y;
            Xs[f4 * 4 + 2][tok] = xv.z;
            Xs[f4 * 4 + 3][tok] = xv.w;
        }
        __syncthreads();
#pragma unroll
        for (int k = 0; k < 16; k++) {
            ulonglong2 w01 = *(const ulonglong2*)&As[k][ty * 4];
            ulonglong2 w23 = *(const ulonglong2*)&As[k][ty * 4 + 2];
            const ulonglong2* xp = (const ulonglong2*)&Xs[k][tx * 8];
            ulonglong2 xA = xp[0], xB = xp[1];
            acc[0][0] = fma2(w01.x, xA.x, acc[0][0]); acc[0][1] = fma2(w01.x, xA.y, acc[0][1]);
            acc[0][2] = fma2(w01.x, xB.x, acc[0][2]); acc[0][3] = fma2(w01.x, xB.y, acc[0][3]);
            acc[1][0] = fma2(w01.y, xA.x, acc[1][0]); acc[1][1] = fma2(w01.y, xA.y, acc[1][1]);
            acc[1][2] = fma2(w01.y, xB.x, acc[1][2]); acc[1][3] = fma2(w01.y, xB.y, acc[1][3]);
            acc[2][0] = fma2(w23.x, xA.x, acc[2][0]); acc[2][1] = fma2(w23.x, xA.y, acc[2][1]);
            acc[2][2] = fma2(w23.x, xB.x, acc[2][2]); acc[2][3] = fma2(w23.x, xB.y, acc[2][3]);
            acc[3][0] = fma2(w23.y, xA.x, acc[3][0]); acc[3][1] = fma2(w23.y, xA.y, acc[3][1]);
            acc[3][2] = fma2(w23.y, xB.x, acc[3][2]); acc[3][3] = fma2(w23.y, xB.y, acc[3][3]);
        }
        __syncthreads();
    }
#pragma unroll
    for (int i = 0; i < 4; i++) {
        int row = m0 + ty * 4 + i;
        float bias = bih[row] + bhh[row];
#pragma unroll
        for (int c = 0; c < 4; c++) {
            float2 f = *(float2*)&acc[i][c];
            int n = n0 + tx * 8 + c * 2;        // even; pair stays inside one t-group
            int tt = n >> 5, bb2 = n & 31;
            float2 o;
            o.x = f.x + bias; o.y = f.y + bias;
            *(float2*)&g_xg[(((size_t)d * SS + tt) * T4H + row) * BB + bb2] = o;
        }
    }
}

// ---------------- persistent BiLSTM recurrence (round-5 verbatim: proven 833us) ----------------
__global__ __launch_bounds__(128, 1) void lstm_kernel(
    const float* __restrict__ WhhF, const float* __restrict__ WhhB) {
    extern __shared__ ull sm8[];
    ull*   W_dup = sm8;                     // [256 k][16 r] {w,w} pairs (4096 ull)
    float* h_s   = (float*)(sm8 + 4096);    // [256 k][32 b]            (4096 ull)
    ull*   part  = sm8 + 8192;              // [4 w][16 r][17 pairs]    (1088 ull)

    int tid = threadIdx.x, bid = blockIdx.x;
    int d = bid >> 6, m = bid & 63;
    const float* Whh = d ? WhhB : WhhF;

    for (int i = tid; i < 4096; i += 128) {
        int r = i & 15, k = i >> 4;
        int gg = r >> 2, uu = r & 3;
        float w = Whh[(size_t)(gg * HH + m * 4 + uu) * HH + k];
        W_dup[k * 16 + r] = pack2(w, w);
    }
    __syncthreads();

    int lane = tid & 31, w = tid >> 5;
    int ggl = lane & 3, bg = lane >> 2;
    const ulonglong2* Wd2 = (const ulonglong2*)W_dup;
    const ulonglong2* H2  = (const ulonglong2*)h_s;
    int u = tid >> 5, b = tid & 31;
    float c_reg = 0.0f;
    unsigned* barD = g_bar + d * SS * 4;
    int mygrp = m >> 4;

    for (int it = 0; it < SS; it++) {
        int t = d ? (SS - 1 - it) : it;

        float xgv[4];
        const float* xgb = g_xg + ((size_t)(d * SS + t) * T4H) * BB;
#pragma unroll
        for (int gg = 0; gg < 4; gg++)
            xgv[gg] = xgb[(size_t)(gg * HH + m * 4 + u) * BB + b];

        if (it > 0) {
            unsigned* cp = barD + (it - 1) * 4 + w;
            unsigned v;
            do {
                asm volatile("ld.acquire.gpu.global.u32 %0, [%1];" : "=r"(v) : "l"(cp) : "memory");
            } while (v < 16u);

            int tp = d ? t + 1 : t - 1;
            const float4* src4 = (const float4*)(g_h + (size_t)(d * SS + tp) * HH * BB);
            float4* dst4 = (float4*)h_s;
#pragma unroll
            for (int j = 0; j < 16; j++) {
                int idx = w * 512 + lane + j * 32;
                dst4[idx] = src4[idx];
            }
            __syncwarp();

            ull a[4][2];
#pragma unroll
            for (int i = 0; i < 4; i++) { a[i][0] = 0ULL; a[i][1] = 0ULL; }
            int k0 = w * 64;
#pragma unroll 8
            for (int k = k0; k < k0 + 64; k++) {
                ulonglong2 w01 = Wd2[k * 8 + ggl * 2];
                ulonglong2 w23 = Wd2[k * 8 + ggl * 2 + 1];
                ulonglong2 hh  = H2[k * 8 + bg];
                a[0][0] = fma2(w01.x, hh.x, a[0][0]); a[0][1] = fma2(w01.x, hh.y, a[0][1]);
                a[1][0] = fma2(w01.y, hh.x, a[1][0]); a[1][1] = fma2(w01.y, hh.y, a[1][1]);
                a[2][0] = fma2(w23.x, hh.x, a[2][0]); a[2][1] = fma2(w23.x, hh.y, a[2][1]);
                a[3][0] = fma2(w23.y, hh.x, a[3][0]); a[3][1] = fma2(w23.y, hh.y, a[3][1]);
            }
#pragma unroll
            for (int i = 0; i < 4; i++) {
                ull* pr = part + (size_t)(w * 16 + ggl * 4 + i) * 17 + bg * 2;
                pr[0] = a[i][0]; pr[1] = a[i][1];
            }
        }
        __syncthreads();

        {
            const float* pf = (const float*)part;
            float g[4];
#pragma unroll
            for (int gg = 0; gg < 4; gg++) {
                float s = xgv[gg];
                if (it > 0) {
                    int r = gg * 4 + u;
#pragma unroll
                    for (int wi = 0; wi < 4; wi++)
                        s += pf[(((size_t)wi * 16 + r) * 17 + (b >> 1)) * 2 + (b & 1)];
                }
                g[gg] = s;
            }
            float iv = fsigmoid(g[0]);
            float fv = fsigmoid(g[1]);
            float gv = ftanh_fast(g[2]);
            float ov = fsigmoid(g[3]);
            c_reg = fv * c_reg + iv * gv;
            g_h[((size_t)(d * SS + t) * HH + m * 4 + u) * BB + b] = ov * ftanh_fast(c_reg);
        }
        __syncthreads();

        if (tid == 0) {
            unsigned* ap = barD + it * 4 + mygrp;
            asm volatile("red.release.gpu.global.add.u32 [%0], %1;" :: "l"(ap), "r"(1u) : "memory");
        }
    }
}

// ---------------- logits: [b][t][tag] = hcat . W_tag[tag] + b_tag ----------------
__global__ __launch_bounds__(256) void logits_kernel(const float* __restrict__ Wtag,
                                                     const float* __restrict__ btag) {
    extern __shared__ float hb[];  // [512 k][32 b]
    int t = blockIdx.x;
    int tid = threadIdx.x;
    for (int dd = 0; dd < 2; dd++) {
        const float4* src = (const float4*)(g_h + (size_t)(dd * SS + t) * HH * BB);
        float4* dst = (float4*)(hb + (size_t)dd * HH * BB);
        for (int i = tid; i < 2048; i += 256) dst[i] = src[i];
    }
    __syncthreads();
    for (int o = tid; o < BB * NT; o += 256) {
        int tag = o >> 5;
        int b = o & 31;
        float acc = btag[tag];
        const float* wr = Wtag + (size_t)tag * (2 * HH);
#pragma unroll 8
        for (int k = 0; k < 2 * HH; k++) acc += hb[k * BB + b] * wr[k];
        g_logits[((size_t)b * SS + t) * NT + tag] = acc;
    }
}

// ---------------- merged CRF forward + Viterbi (grid 32 x 2); loss via atomicAdd ----------------
__global__ void crf_vit_kernel(const int* __restrict__ mask, const int* __restrict__ labels,
                               const float* __restrict__ trans, float* __restrict__ out) {
    __shared__ float tr[NT * NT];
    __shared__ float st[NT];
    int b = blockIdx.x, j = threadIdx.x;
    for (int i = j; i < NT * NT; i += 32) tr[i] = trans[i];
    __syncthreads();

    if (blockIdx.y == 0) {
        if (j < NT) st[j] = g_logits[((size_t)b * SS) * NT + j] + tr[TSTART * NT + j];
        __syncthreads();
        for (int t = 1; t < SS; t++) {
            int mt = mask[b * SS + t];
            float nv = 0.0f;
            if (j < NT) {
                float mx = -1e30f;
#pragma unroll
                for (int i = 0; i < NT; i++) mx = fmaxf(mx, st[i] + tr[i * NT + j]);
                float sum = 0.0f;
#pragma unroll
                for (int i = 0; i < NT; i++) sum += __expf(st[i] + tr[i * NT + j] - mx);
                nv = mx + __logf(sum) + g_logits[((size_t)b * SS + t) * NT + j];
            }
            __syncthreads();
            if (j < NT && mt > 0) st[j] = nv;
            __syncthreads();
        }
        if (j == 0) {
            float mx = -1e30f;
            for (int i = 0; i < NT; i++) mx = fmaxf(mx, st[i] + tr[i * NT + TSTOP]);
            float sum = 0.0f;
            for (int i = 0; i < NT; i++) sum += __expf(st[i] + tr[i * NT + TSTOP] - mx);
            float logZ = mx + __logf(sum);
            float gold = 0.0f;
            int prev = TSTART, len = 0;
            for (int t = 0; t < SS; t++) {
                int lab = labels[b * SS + t];
                if (mask[b * SS + t] > 0) {
                    gold += tr[prev * NT + lab] + g_logits[((size_t)b * SS + t) * NT + lab];
                    len++;
                }
                prev = lab;
            }
            int last = labels[b * SS + len - 1];
            gold += tr[last * NT + TSTOP];
            atomicAdd(out, (logZ - gold) * (1.0f / (float)BB));
        }
    } else {
        if (j < NT) st[j] = g_logits[((size_t)b * SS) * NT + j] + tr[TSTART * NT + j];
        __syncthreads();
        for (int t = 1; t < SS; t++) {
            int mt = mask[b * SS + t];
            float nv = 0.0f;
            int arg = j;
            if (j < NT) {
                float best = -1e30f;
                int bi = 0;
#pragma unroll
                for (int i = 0; i < NT; i++) {
                    float v = st[i] + tr[i * NT + j];
                    if (v > best) { best = v; bi = i; }  // strict '>' => first max (jnp.argmax)
                }
                nv = best + g_logits[((size_t)b * SS + t) * NT + j];
                if (mt > 0) arg = bi;
            }
            __syncthreads();
            if (j < NT) {
                if (mt > 0) st[j] = nv;
                g_ptr[((size_t)b * SS + t) * NT + j] = arg;
            }
            __syncthreads();
        }
        if (j == 0) {
            float best = -1e30f;
            int bl = 0;
            for (int i = 0; i < NT; i++) {
                float v = st[i] + tr[i * NT + TSTOP];
                if (v > best) { best = v; bl = i; }
            }
            int tag = bl;
            for (int t = SS - 1; t >= 1; t--) {
                out[1 + b * SS + t] = (float)(mask[b * SS + t] > 0 ? tag : 0);
                tag = g_ptr[((size_t)b * SS + t) * NT + tag];
            }
            out[1 + b * SS + 0] = (float)(mask[b * SS + 0] > 0 ? tag : 0);
        }
    }
}

extern "C" void kernel_launch(void* const* d_in, const int* in_sizes, int n_in,
                              void* d_out, int out_size) {
    int o = (in_sizes[4] == 1) ? 0 : -1;  // data_type scalar present or dropped
    const int*   word   = (const int*)d_in[0];
    const int*   mask   = (const int*)d_in[1];
    const int*   labels = (const int*)d_in[2];
    const float* emb    = (const float*)d_in[5 + o];
    const float* WihF   = (const float*)d_in[6 + o];
    const float* WhhF   = (const float*)d_in[7 + o];
    const float* bihF   = (const float*)d_in[8 + o];
    const float* bhhF   = (const float*)d_in[9 + o];
    const float* WihB   = (const float*)d_in[10 + o];
    const float* WhhB   = (const float*)d_in[11 + o];
    const float* bihB   = (const float*)d_in[12 + o];
    const float* bhhB   = (const float*)d_in[13 + o];
    const float* Wtag   = (const float*)d_in[14 + o];
    const float* btag   = (const float*)d_in[15 + o];
    const float* trans  = (const float*)d_in[16 + o];
    float* out = (float*)d_out;

    const int lstm_smem = (4096 + 4096 + 1088) * 8;  // 74240 B
    cudaFuncSetAttribute(lstm_kernel, cudaFuncAttributeMaxDynamicSharedMemorySize, lstm_smem);
    cudaFuncSetAttribute(logits_kernel, cudaFuncAttributeMaxDynamicSharedMemorySize, 65536);

    embed_kernel<<<(BB * SS * (EP / 4) + 255) / 256, 256>>>(word, mask, emb, out);
    {
        dim3 grid(BB * SS / 128, T4H / 64, 2);
        gemm_xg_kernel<<<grid, 256>>>(WihF, WihB, bihF, bhhF, bihB, bhhB);
    }
    lstm_kernel<<<128, 128, lstm_smem>>>(WhhF, WhhB);
    logits_kernel<<<SS, 256, 65536>>>(Wtag, btag);
    crf_vit_kernel<<<dim3(BB, 2), 32>>>(mask, labels, trans, out);
}

// round 12
// speedup vs baseline: 1.8060x; 1.0099x over previous
#include <cuda_runtime.h>
#include <math.h>

#define BB 32
#define SS 256
#define EE 300
#define EP 304
#define HH 256
#define T4H 1024
#define NT 19
#define TSTART 17
#define TSTOP 18

typedef unsigned long long ull;

__device__ __forceinline__ ull fma2(ull a, ull b, ull c) {
    ull d;
    asm("fma.rn.f32x2 %0, %1, %2, %3;" : "=l"(d) : "l"(a), "l"(b), "l"(c));
    return d;
}
__device__ __forceinline__ ull pack2(float lo, float hi) {
    ull r;
    asm("mov.b64 %0, {%1, %2};" : "=l"(r) : "f"(lo), "f"(hi));
    return r;
}
__device__ __forceinline__ float fsigmoid(float x) {
    return 1.0f / (1.0f + __expf(-x));
}
__device__ __forceinline__ float ftanh_fast(float x) {
    return 1.0f - 2.0f / (__expf(2.0f * x) + 1.0f);
}

// ---------------- device scratch (no cudaMalloc allowed) ----------------
__device__ float    g_X[(size_t)BB * SS * EP];            // [n][e], n = t*32 + b
__device__ float    g_xg[(size_t)2 * SS * T4H * BB];      // [d][t][row][b]
__device__ float    g_h[(size_t)2 * SS * HH * BB];        // [d][t][k][b]
__device__ float    g_logits[(size_t)BB * SS * NT];       // [b][t*NT+tag] contiguous per b
__device__ unsigned g_bar[2 * SS * 4];                    // [dir][step][group] arrival counters

// ---------------- embedding gather + mask -> padded X; also inits out[0] + counters ----------------
__global__ void embed_kernel(const int* __restrict__ word, const int* __restrict__ mask,
                             const float* __restrict__ emb, float* __restrict__ out) {
    int idx = blockIdx.x * blockDim.x + threadIdx.x;
    if (idx == 0) out[0] = 0.0f;                 // crf blocks atomicAdd into this
    if (idx < 2 * SS * 4) g_bar[idx] = 0u;       // reset per-step barrier counters
    int total = BB * SS * (EP / 4);
    if (idx >= total) return;
    int n = idx / (EP / 4), q = idx - n * (EP / 4);
    int t = n >> 5, b = n & 31;
    int w = word[b * SS + t];
    float m = (float)mask[b * SS + t];
    int e = q * 4;
    float4 v;
    if (e < EE) {
        float4 ev = *(const float4*)(emb + (size_t)w * EE + e);
        v.x = ev.x * m; v.y = ev.y * m; v.z = ev.z * m; v.w = ev.w * m;
    } else {
        v.x = v.y = v.z = v.w = 0.0f;
    }
    ((float4*)g_X)[(size_t)n * (EP / 4) + q] = v;
}

// ---------------- input-transform GEMM (f32x2, 64x128 tiles): xg = X @ Wih_d.T + bih + bhh ----------------
__global__ __launch_bounds__(256) void gemm_xg_kernel(
    const float* __restrict__ WihF, const float* __restrict__ WihB,
    const float* __restrict__ bihF, const float* __restrict__ bhhF,
    const float* __restrict__ bihB, const float* __restrict__ bhhB) {
    __shared__ ull   As[16][64];
    __shared__ float Xs[16][132];
    int d = blockIdx.z;
    const float* Wih = d ? WihB : WihF;
    const float* bih = d ? bihB : bihF;
    const float* bhh = d ? bhhB : bhhF;
    int m0 = blockIdx.y * 64, n0 = blockIdx.x * 128;
    int tid = threadIdx.x;
    int lmA = tid >> 2, kqA = (tid & 3) * 4;
    int tok = tid >> 1, f4b = (tid & 1) * 2;
    int tx = tid & 15, ty = tid >> 4;
    ull acc[4][4];
#pragma unroll
    for (int i = 0; i < 4; i++)
#pragma unroll
        for (int j = 0; j < 4; j++) acc[i][j] = 0ULL;

    for (int e0 = 0; e0 < EP; e0 += 16) {
        float4 a;
        if (e0 + kqA < EE) {
            a = *(const float4*)(Wih + (size_t)(m0 + lmA) * EE + e0 + kqA);
        } else {
            a.x = a.y = a.z = a.w = 0.0f;
        }
        As[kqA + 0][lmA] = pack2(a.x, a.x);
        As[kqA + 1][lmA] = pack2(a.y, a.y);
        As[kqA + 2][lmA] = pack2(a.z, a.z);
        As[kqA + 3][lmA] = pack2(a.w, a.w);
#pragma unroll
        for (int q = 0; q < 2; q++) {
            int f4 = f4b + q;
            float4 xv = *(const float4*)(g_X + (size_t)(n0 + tok) * EP + e0 + f4 * 4);
            Xs[f4 * 4 + 0][tok] = xv.x;
            Xs[f4 * 4 + 1][tok] = xv.y;
            Xs[f4 * 4 + 2][tok] = xv.z;
            Xs[f4 * 4 + 3][tok] = xv.w;
        }
        __syncthreads();
#pragma unroll
        for (int k = 0; k < 16; k++) {
            ulonglong2 w01 = *(const ulonglong2*)&As[k][ty * 4];
            ulonglong2 w23 = *(const ulonglong2*)&As[k][ty * 4 + 2];
            const ulonglong2* xp = (const ulonglong2*)&Xs[k][tx * 8];
            ulonglong2 xA = xp[0], xB = xp[1];
            acc[0][0] = fma2(w01.x, xA.x, acc[0][0]); acc[0][1] = fma2(w01.x, xA.y, acc[0][1]);
            acc[0][2] = fma2(w01.x, xB.x, acc[0][2]); acc[0][3] = fma2(w01.x, xB.y, acc[0][3]);
            acc[1][0] = fma2(w01.y, xA.x, acc[1][0]); acc[1][1] = fma2(w01.y, xA.y, acc[1][1]);
            acc[1][2] = fma2(w01.y, xB.x, acc[1][2]); acc[1][3] = fma2(w01.y, xB.y, acc[1][3]);
            acc[2][0] = fma2(w23.x, xA.x, acc[2][0]); acc[2][1] = fma2(w23.x, xA.y, acc[2][1]);
            acc[2][2] = fma2(w23.x, xB.x, acc[2][2]); acc[2][3] = fma2(w23.x, xB.y, acc[2][3]);
            acc[3][0] = fma2(w23.y, xA.x, acc[3][0]); acc[3][1] = fma2(w23.y, xA.y, acc[3][1]);
            acc[3][2] = fma2(w23.y, xB.x, acc[3][2]); acc[3][3] = fma2(w23.y, xB.y, acc[3][3]);
        }
        __syncthreads();
    }
#pragma unroll
    for (int i = 0; i < 4; i++) {
        int row = m0 + ty * 4 + i;
        float bias = bih[row] + bhh[row];
#pragma unroll
        for (int c = 0; c < 4; c++) {
            float2 f = *(float2*)&acc[i][c];
            int n = n0 + tx * 8 + c * 2;
            int tt = n >> 5, bb2 = n & 31;
            float2 o;
            o.x = f.x + bias; o.y = f.y + bias;
            *(float2*)&g_xg[(((size_t)d * SS + tt) * T4H + row) * BB + bb2] = o;
        }
    }
}

// ---------------- persistent BiLSTM recurrence (round-5 verbatim: proven 833us) ----------------
__global__ __launch_bounds__(128, 1) void lstm_kernel(
    const float* __restrict__ WhhF, const float* __restrict__ WhhB) {
    extern __shared__ ull sm8[];
    ull*   W_dup = sm8;
    float* h_s   = (float*)(sm8 + 4096);
    ull*   part  = sm8 + 8192;

    int tid = threadIdx.x, bid = blockIdx.x;
    int d = bid >> 6, m = bid & 63;
    const float* Whh = d ? WhhB : WhhF;

    for (int i = tid; i < 4096; i += 128) {
        int r = i & 15, k = i >> 4;
        int gg = r >> 2, uu = r & 3;
        float w = Whh[(size_t)(gg * HH + m * 4 + uu) * HH + k];
        W_dup[k * 16 + r] = pack2(w, w);
    }
    __syncthreads();

    int lane = tid & 31, w = tid >> 5;
    int ggl = lane & 3, bg = lane >> 2;
    const ulonglong2* Wd2 = (const ulonglong2*)W_dup;
    const ulonglong2* H2  = (const ulonglong2*)h_s;
    int u = tid >> 5, b = tid & 31;
    float c_reg = 0.0f;
    unsigned* barD = g_bar + d * SS * 4;
    int mygrp = m >> 4;

    for (int it = 0; it < SS; it++) {
        int t = d ? (SS - 1 - it) : it;

        float xgv[4];
        const float* xgb = g_xg + ((size_t)(d * SS + t) * T4H) * BB;
#pragma unroll
        for (int gg = 0; gg < 4; gg++)
            xgv[gg] = xgb[(size_t)(gg * HH + m * 4 + u) * BB + b];

        if (it > 0) {
            unsigned* cp = barD + (it - 1) * 4 + w;
            unsigned v;
            do {
                asm volatile("ld.acquire.gpu.global.u32 %0, [%1];" : "=r"(v) : "l"(cp) : "memory");
            } while (v < 16u);

            int tp = d ? t + 1 : t - 1;
            const float4* src4 = (const float4*)(g_h + (size_t)(d * SS + tp) * HH * BB);
            float4* dst4 = (float4*)h_s;
#pragma unroll
            for (int j = 0; j < 16; j++) {
                int idx = w * 512 + lane + j * 32;
                dst4[idx] = src4[idx];
            }
            __syncwarp();

            ull a[4][2];
#pragma unroll
            for (int i = 0; i < 4; i++) { a[i][0] = 0ULL; a[i][1] = 0ULL; }
            int k0 = w * 64;
#pragma unroll 8
            for (int k = k0; k < k0 + 64; k++) {
                ulonglong2 w01 = Wd2[k * 8 + ggl * 2];
                ulonglong2 w23 = Wd2[k * 8 + ggl * 2 + 1];
                ulonglong2 hh  = H2[k * 8 + bg];
                a[0][0] = fma2(w01.x, hh.x, a[0][0]); a[0][1] = fma2(w01.x, hh.y, a[0][1]);
                a[1][0] = fma2(w01.y, hh.x, a[1][0]); a[1][1] = fma2(w01.y, hh.y, a[1][1]);
                a[2][0] = fma2(w23.x, hh.x, a[2][0]); a[2][1] = fma2(w23.x, hh.y, a[2][1]);
                a[3][0] = fma2(w23.y, hh.x, a[3][0]); a[3][1] = fma2(w23.y, hh.y, a[3][1]);
            }
#pragma unroll
            for (int i = 0; i < 4; i++) {
                ull* pr = part + (size_t)(w * 16 + ggl * 4 + i) * 17 + bg * 2;
                pr[0] = a[i][0]; pr[1] = a[i][1];
            }
        }
        __syncthreads();

        {
            const float* pf = (const float*)part;
            float g[4];
#pragma unroll
            for (int gg = 0; gg < 4; gg++) {
                float s = xgv[gg];
                if (it > 0) {
                    int r = gg * 4 + u;
#pragma unroll
                    for (int wi = 0; wi < 4; wi++)
                        s += pf[(((size_t)wi * 16 + r) * 17 + (b >> 1)) * 2 + (b & 1)];
                }
                g[gg] = s;
            }
            float iv = fsigmoid(g[0]);
            float fv = fsigmoid(g[1]);
            float gv = ftanh_fast(g[2]);
            float ov = fsigmoid(g[3]);
            c_reg = fv * c_reg + iv * gv;
            g_h[((size_t)(d * SS + t) * HH + m * 4 + u) * BB + b] = ov * ftanh_fast(c_reg);
        }
        __syncthreads();

        if (tid == 0) {
            unsigned* ap = barD + it * 4 + mygrp;
            asm volatile("red.release.gpu.global.add.u32 [%0], %1;" :: "l"(ap), "r"(1u) : "memory");
        }
    }
}

// ---------------- logits: Wtag staged in smem; [b][t][tag] = hcat . W_tag[tag] + b_tag ----------------
__global__ __launch_bounds__(256) void logits_kernel(const float* __restrict__ Wtag,
                                                     const float* __restrict__ btag) {
    extern __shared__ float hb[];          // [512 k][32 b] = 64KB, then wt [19][512] = 38KB
    float* wt = hb + 512 * 32;
    int t = blockIdx.x;
    int tid = threadIdx.x;
    for (int dd = 0; dd < 2; dd++) {
        const float4* src = (const float4*)(g_h + (size_t)(dd * SS + t) * HH * BB);
        float4* dst = (float4*)(hb + (size_t)dd * HH * BB);
        for (int i = tid; i < 2048; i += 256) dst[i] = src[i];
    }
    // stage Wtag (19*512 floats = 2432 float4)
    {
        const float4* ws = (const float4*)Wtag;
        float4* wd = (float4*)wt;
        for (int i = tid; i < 2432; i += 256) wd[i] = ws[i];
    }
    __syncthreads();
    for (int o = tid; o < BB * NT; o += 256) {
        int tag = o >> 5;                   // warp-uniform -> wt reads broadcast
        int b = o & 31;
        float acc = btag[tag];
        const float* wr = wt + tag * 512;
#pragma unroll 8
        for (int k = 0; k < 2 * HH; k++) acc += hb[k * BB + b] * wr[k];
        g_logits[((size_t)b * SS + t) * NT + tag] = acc;
    }
}

// ---------------- merged CRF forward + Viterbi (grid 32 x 2), fully smem-staged ----------------
// dynamic smem layout (floats): tr[364] | lg[4864] | msk[256] | lbl[256] | ptr_s[4864]
__global__ void crf_vit_kernel(const int* __restrict__ mask, const int* __restrict__ labels,
                               const float* __restrict__ trans, float* __restrict__ out) {
    extern __shared__ float smc[];
    float* tr  = smc;                      // 361 used, 364 reserved (16B align)
    float* lg  = smc + 364;                // logits for this b: [t*NT+j]
    int*   msk = (int*)(smc + 364 + 4864); // mask[b][:]
    int*   lbl = msk + 256;                // labels[b][:]
    int*   ptr_s = msk + 512;              // viterbi backpointers [t*NT+j]
    __shared__ float st[NT];

    int b = blockIdx.x, j = threadIdx.x;
    for (int i = j; i < NT * NT; i += 32) tr[i] = trans[i];
    // stage this batch's logits (19456B, coalesced float4)
    {
        const float4* src = (const float4*)(g_logits + (size_t)b * SS * NT);
        float4* dst = (float4*)lg;
        for (int i = j; i < SS * NT / 4; i += 32) dst[i] = src[i];
    }
    for (int i = j; i < SS; i += 32) {
        msk[i] = mask[b * SS + i];
        lbl[i] = labels[b * SS + i];
    }
    __syncthreads();

    if (blockIdx.y == 0) {
        // ---- CRF NLL ----
        if (j < NT) st[j] = lg[j] + tr[TSTART * NT + j];
        __syncthreads();
        for (int t = 1; t < SS; t++) {
            int mt = msk[t];
            float nv = 0.0f;
            if (j < NT) {
                float mx = -1e30f;
#pragma unroll
                for (int i = 0; i < NT; i++) mx = fmaxf(mx, st[i] + tr[i * NT + j]);
                float sum = 0.0f;
#pragma unroll
                for (int i = 0; i < NT; i++) sum += __expf(st[i] + tr[i * NT + j] - mx);
                nv = mx + __logf(sum) + lg[t * NT + j];
            }
            __syncthreads();
            if (j < NT && mt > 0) st[j] = nv;
            __syncthreads();
        }
        if (j == 0) {
            float mx = -1e30f;
            for (int i = 0; i < NT; i++) mx = fmaxf(mx, st[i] + tr[i * NT + TSTOP]);
            float sum = 0.0f;
            for (int i = 0; i < NT; i++) sum += __expf(st[i] + tr[i * NT + TSTOP] - mx);
            float logZ = mx + __logf(sum);
            float gold = 0.0f;
            int prev = TSTART, len = 0;
            for (int t = 0; t < SS; t++) {
                int lab = lbl[t];
                if (msk[t] > 0) {
                    gold += tr[prev * NT + lab] + lg[t * NT + lab];
                    len++;
                }
                prev = lab;
            }
            int last = lbl[len - 1];
            gold += tr[last * NT + TSTOP];
            atomicAdd(out, (logZ - gold) * (1.0f / (float)BB));
        }
    } else {
        // ---- Viterbi (backpointers stay in smem) ----
        if (j < NT) st[j] = lg[j] + tr[TSTART * NT + j];
        __syncthreads();
        for (int t = 1; t < SS; t++) {
            int mt = msk[t];
            float nv = 0.0f;
            int arg = j;
            if (j < NT) {
                float best = -1e30f;
                int bi = 0;
#pragma unroll
                for (int i = 0; i < NT; i++) {
                    float v = st[i] + tr[i * NT + j];
                    if (v > best) { best = v; bi = i; }  // strict '>' => first max (jnp.argmax)
                }
                nv = best + lg[t * NT + j];
                if (mt > 0) arg = bi;
            }
            __syncthreads();
            if (j < NT) {
                if (mt > 0) st[j] = nv;
                ptr_s[t * NT + j] = arg;
            }
            __syncthreads();
        }
        if (j == 0) {
            float best = -1e30f;
            int bl = 0;
            for (int i = 0; i < NT; i++) {
                float v = st[i] + tr[i * NT + TSTOP];
                if (v > best) { best = v; bl = i; }
            }
            int tag = bl;
            for (int t = SS - 1; t >= 1; t--) {
                out[1 + b * SS + t] = (float)(msk[t] > 0 ? tag : 0);
                tag = ptr_s[t * NT + tag];
            }
            out[1 + b * SS + 0] = (float)(msk[0] > 0 ? tag : 0);
        }
    }
}

extern "C" void kernel_launch(void* const* d_in, const int* in_sizes, int n_in,
                              void* d_out, int out_size) {
    int o = (in_sizes[4] == 1) ? 0 : -1;  // data_type scalar present or dropped
    const int*   word   = (const int*)d_in[0];
    const int*   mask   = (const int*)d_in[1];
    const int*   labels = (const int*)d_in[2];
    const float* emb    = (const float*)d_in[5 + o];
    const float* WihF   = (const float*)d_in[6 + o];
    const float* WhhF   = (const float*)d_in[7 + o];
    const float* bihF   = (const float*)d_in[8 + o];
    const float* bhhF   = (const float*)d_in[9 + o];
    const float* WihB   = (const float*)d_in[10 + o];
    const float* WhhB   = (const float*)d_in[11 + o];
    const float* bihB   = (const float*)d_in[12 + o];
    const float* bhhB   = (const float*)d_in[13 + o];
    const float* Wtag   = (const float*)d_in[14 + o];
    const float* btag   = (const float*)d_in[15 + o];
    const float* trans  = (const float*)d_in[16 + o];
    float* out = (float*)d_out;

    const int lstm_smem = (4096 + 4096 + 1088) * 8;           // 74240 B
    const int logits_smem = (512 * 32 + 19 * 512) * 4;        // 104448 B
    const int crf_smem = (364 + 4864 + 256 + 256 + 4864) * 4; // 42416 B
    cudaFuncSetAttribute(lstm_kernel, cudaFuncAttributeMaxDynamicSharedMemorySize, lstm_smem);
    cudaFuncSetAttribute(logits_kernel, cudaFuncAttributeMaxDynamicSharedMemorySize, logits_smem);

    embed_kernel<<<(BB * SS * (EP / 4) + 255) / 256, 256>>>(word, mask, emb, out);
    {
        dim3 grid(BB * SS / 128, T4H / 64, 2);
        gemm_xg_kernel<<<grid, 256>>>(WihF, WihB, bihF, bhhF, bihB, bhhB);
    }
    lstm_kernel<<<128, 128, lstm_smem>>>(WhhF, WhhB);
    logits_kernel<<<SS, 256, logits_smem>>>(Wtag, btag);
    crf_vit_kernel<<<dim3(BB, 2), 32, crf_smem>>>(mask, labels, trans, out);
}

// round 13
// speedup vs baseline: 2.0713x; 1.1469x over previous
#include <cuda_runtime.h>
#include <math.h>

#define BB 32
#define SS 256
#define EE 300
#define EP 304
#define HH 256
#define T4H 1024
#define NT 19
#define TSTART 17
#define TSTOP 18

typedef unsigned long long ull;

__device__ __forceinline__ ull fma2(ull a, ull b, ull c) {
    ull d;
    asm("fma.rn.f32x2 %0, %1, %2, %3;" : "=l"(d) : "l"(a), "l"(b), "l"(c));
    return d;
}
__device__ __forceinline__ ull pack2(float lo, float hi) {
    ull r;
    asm("mov.b64 %0, {%1, %2};" : "=l"(r) : "f"(lo), "f"(hi));
    return r;
}
__device__ __forceinline__ float fsigmoid(float x) {
    return 1.0f / (1.0f + __expf(-x));
}
__device__ __forceinline__ float ftanh_fast(float x) {
    return 1.0f - 2.0f / (__expf(2.0f * x) + 1.0f);
}

// ---------------- device scratch (no cudaMalloc allowed) ----------------
__device__ float    g_X[(size_t)BB * SS * EP];            // [n][e], n = t*32 + b
__device__ float    g_xg[(size_t)2 * SS * T4H * BB];      // [d][t][row][b]
__device__ float    g_h[(size_t)2 * SS * HH * BB];        // [d][t][k][b]
__device__ float    g_logits[(size_t)BB * SS * NT];       // [b][t*NT+tag]
__device__ unsigned g_bar[2 * SS * 4];                    // [dir][step][group] arrival counters

// ---------------- embedding gather + mask -> padded X; inits out[0] + counters ----------------
__global__ void embed_kernel(const int* __restrict__ word, const int* __restrict__ mask,
                             const float* __restrict__ emb, float* __restrict__ out) {
    int idx = blockIdx.x * blockDim.x + threadIdx.x;
    if (idx == 0) out[0] = 0.0f;
    if (idx < 2 * SS * 4) g_bar[idx] = 0u;
    int total = BB * SS * (EP / 4);
    if (idx >= total) return;
    int n = idx / (EP / 4), q = idx - n * (EP / 4);
    int t = n >> 5, b = n & 31;
    int w = word[b * SS + t];
    float m = (float)mask[b * SS + t];
    int e = q * 4;
    float4 v;
    if (e < EE) {
        float4 ev = *(const float4*)(emb + (size_t)w * EE + e);
        v.x = ev.x * m; v.y = ev.y * m; v.z = ev.z * m; v.w = ev.w * m;
    } else {
        v.x = v.y = v.z = v.w = 0.0f;
    }
    ((float4*)g_X)[(size_t)n * (EP / 4) + q] = v;
}

// ---------------- input-transform GEMM: double-buffered, conflict-free f32x2 ----------------
// 64 rows x 128 tokens per block; thread tile = rows {2ty,2ty+1,32+2ty,33+2ty} x
// tokens {4tx..4tx+3, 64+4tx..64+4tx+3}. All LDS.128 are 16B-lane-stride or broadcast.
__global__ __launch_bounds__(256) void gemm_xg_kernel(
    const float* __restrict__ WihF, const float* __restrict__ WihB,
    const float* __restrict__ bihF, const float* __restrict__ bhhF,
    const float* __restrict__ bihB, const float* __restrict__ bhhB) {
    __shared__ ull   As[2][16][64];      // [buf][k][row] duplicated {w,w}  (16KB)
    __shared__ float Xs[2][16][132];     // [buf][k][token], pitch 132      (16.5KB)
    int d = blockIdx.z;
    const float* Wih = d ? WihB : WihF;
    const float* bih = d ? bihB : bihF;
    const float* bhh = d ? bhhB : bhhF;
    int m0 = blockIdx.y * 64, n0 = blockIdx.x * 128;
    int tid = threadIdx.x;
    int lmA = tid >> 2, kqA = (tid & 3) * 4;   // W staging: row lmA, k-offset kqA
    int tok = tid >> 1, f4b = (tid & 1) * 2;   // X staging: token tok, float4 slots f4b..f4b+1
    int tx = tid & 15, ty = tid >> 4;

    ull acc[4][4];
#pragma unroll
    for (int i = 0; i < 4; i++)
#pragma unroll
        for (int j = 0; j < 4; j++) acc[i][j] = 0ULL;

    float4 wv, xv0, xv1;
    // prologue: load tile 0
    {
        if (kqA < EE) wv = *(const float4*)(Wih + (size_t)(m0 + lmA) * EE + kqA);
        else { wv.x = wv.y = wv.z = wv.w = 0.0f; }
        xv0 = *(const float4*)(g_X + (size_t)(n0 + tok) * EP + f4b * 4);
        xv1 = *(const float4*)(g_X + (size_t)(n0 + tok) * EP + f4b * 4 + 4);
    }
    // store tile 0 into buf 0
    As[0][kqA + 0][lmA] = pack2(wv.x, wv.x);
    As[0][kqA + 1][lmA] = pack2(wv.y, wv.y);
    As[0][kqA + 2][lmA] = pack2(wv.z, wv.z);
    As[0][kqA + 3][lmA] = pack2(wv.w, wv.w);
    Xs[0][f4b * 4 + 0][tok] = xv0.x; Xs[0][f4b * 4 + 1][tok] = xv0.y;
    Xs[0][f4b * 4 + 2][tok] = xv0.z; Xs[0][f4b * 4 + 3][tok] = xv0.w;
    Xs[0][f4b * 4 + 4][tok] = xv1.x; Xs[0][f4b * 4 + 5][tok] = xv1.y;
    Xs[0][f4b * 4 + 6][tok] = xv1.z; Xs[0][f4b * 4 + 7][tok] = xv1.w;
    __syncthreads();

    const int NTILE = EP / 16;  // 19
    for (int i = 0; i < NTILE; i++) {
        int cb = i & 1, nb = (i + 1) & 1;
        if (i + 1 < NTILE) {
            int e0 = (i + 1) * 16;
            if (e0 + kqA < EE) wv = *(const float4*)(Wih + (size_t)(m0 + lmA) * EE + e0 + kqA);
            else { wv.x = wv.y = wv.z = wv.w = 0.0f; }
            xv0 = *(const float4*)(g_X + (size_t)(n0 + tok) * EP + e0 + f4b * 4);
            xv1 = *(const float4*)(g_X + (size_t)(n0 + tok) * EP + e0 + f4b * 4 + 4);
        }
#pragma unroll
        for (int k = 0; k < 16; k++) {
            ulonglong2 wA = *(const ulonglong2*)&As[cb][k][ty * 2];        // rows 2ty,2ty+1
            ulonglong2 wB = *(const ulonglong2*)&As[cb][k][32 + ty * 2];   // rows 32+2ty,33+2ty
            ulonglong2 xA = *(const ulonglong2*)&Xs[cb][k][tx * 4];        // tokens 4tx..4tx+3
            ulonglong2 xB = *(const ulonglong2*)&Xs[cb][k][64 + tx * 4];   // tokens 64+4tx..
            acc[0][0] = fma2(wA.x, xA.x, acc[0][0]); acc[0][1] = fma2(wA.x, xA.y, acc[0][1]);
            acc[0][2] = fma2(wA.x, xB.x, acc[0][2]); acc[0][3] = fma2(wA.x, xB.y, acc[0][3]);
            acc[1][0] = fma2(wA.y, xA.x, acc[1][0]); acc[1][1] = fma2(wA.y, xA.y, acc[1][1]);
            acc[1][2] = fma2(wA.y, xB.x, acc[1][2]); acc[1][3] = fma2(wA.y, xB.y, acc[1][3]);
            acc[2][0] = fma2(wB.x, xA.x, acc[2][0]); acc[2][1] = fma2(wB.x, xA.y, acc[2][1]);
            acc[2][2] = fma2(wB.x, xB.x, acc[2][2]); acc[2][3] = fma2(wB.x, xB.y, acc[2][3]);
            acc[3][0] = fma2(wB.y, xA.x, acc[3][0]); acc[3][1] = fma2(wB.y, xA.y, acc[3][1]);
            acc[3][2] = fma2(wB.y, xB.x, acc[3][2]); acc[3][3] = fma2(wB.y, xB.y, acc[3][3]);
        }
        if (i + 1 < NTILE) {
            As[nb][kqA + 0][lmA] = pack2(wv.x, wv.x);
            As[nb][kqA + 1][lmA] = pack2(wv.y, wv.y);
            As[nb][kqA + 2][lmA] = pack2(wv.z, wv.z);
            As[nb][kqA + 3][lmA] = pack2(wv.w, wv.w);
            Xs[nb][f4b * 4 + 0][tok] = xv0.x; Xs[nb][f4b * 4 + 1][tok] = xv0.y;
            Xs[nb][f4b * 4 + 2][tok] = xv0.z; Xs[nb][f4b * 4 + 3][tok] = xv0.w;
            Xs[nb][f4b * 4 + 4][tok] = xv1.x; Xs[nb][f4b * 4 + 5][tok] = xv1.y;
            Xs[nb][f4b * 4 + 6][tok] = xv1.z; Xs[nb][f4b * 4 + 7][tok] = xv1.w;
        }
        __syncthreads();
    }

    int rows[4] = {m0 + ty * 2, m0 + ty * 2 + 1, m0 + 32 + ty * 2, m0 + 33 + ty * 2};
#pragma unroll
    for (int i = 0; i < 4; i++) {
        int row = rows[i];
        float bias = bih[row] + bhh[row];
#pragma unroll
        for (int c = 0; c < 4; c++) {
            float2 f = *(float2*)&acc[i][c];
            int n = n0 + (c < 2 ? tx * 4 + c * 2 : 64 + tx * 4 + (c - 2) * 2);
            int tt = n >> 5, bb2 = n & 31;
            float2 o;
            o.x = f.x + bias; o.y = f.y + bias;
            *(float2*)&g_xg[(((size_t)d * SS + tt) * T4H + row) * BB + bb2] = o;
        }
    }
}

// ---------------- persistent BiLSTM recurrence (round-5 verbatim) ----------------
__global__ __launch_bounds__(128, 1) void lstm_kernel(
    const float* __restrict__ WhhF, const float* __restrict__ WhhB) {
    extern __shared__ ull sm8[];
    ull*   W_dup = sm8;
    float* h_s   = (float*)(sm8 + 4096);
    ull*   part  = sm8 + 8192;

    int tid = threadIdx.x, bid = blockIdx.x;
    int d = bid >> 6, m = bid & 63;
    const float* Whh = d ? WhhB : WhhF;

    for (int i = tid; i < 4096; i += 128) {
        int r = i & 15, k = i >> 4;
        int gg = r >> 2, uu = r & 3;
        float w = Whh[(size_t)(gg * HH + m * 4 + uu) * HH + k];
        W_dup[k * 16 + r] = pack2(w, w);
    }
    __syncthreads();

    int lane = tid & 31, w = tid >> 5;
    int ggl = lane & 3, bg = lane >> 2;
    const ulonglong2* Wd2 = (const ulonglong2*)W_dup;
    const ulonglong2* H2  = (const ulonglong2*)h_s;
    int u = tid >> 5, b = tid & 31;
    float c_reg = 0.0f;
    unsigned* barD = g_bar + d * SS * 4;
    int mygrp = m >> 4;

    for (int it = 0; it < SS; it++) {
        int t = d ? (SS - 1 - it) : it;

        float xgv[4];
        const float* xgb = g_xg + ((size_t)(d * SS + t) * T4H) * BB;
#pragma unroll
        for (int gg = 0; gg < 4; gg++)
            xgv[gg] = xgb[(size_t)(gg * HH + m * 4 + u) * BB + b];

        if (it > 0) {
            unsigned* cp = barD + (it - 1) * 4 + w;
            unsigned v;
            do {
                asm volatile("ld.acquire.gpu.global.u32 %0, [%1];" : "=r"(v) : "l"(cp) : "memory");
            } while (v < 16u);

            int tp = d ? t + 1 : t - 1;
            const float4* src4 = (const float4*)(g_h + (size_t)(d * SS + tp) * HH * BB);
            float4* dst4 = (float4*)h_s;
#pragma unroll
            for (int j = 0; j < 16; j++) {
                int idx = w * 512 + lane + j * 32;
                dst4[idx] = src4[idx];
            }
            __syncwarp();

            ull a[4][2];
#pragma unroll
            for (int i = 0; i < 4; i++) { a[i][0] = 0ULL; a[i][1] = 0ULL; }
            int k0 = w * 64;
#pragma unroll 8
            for (int k = k0; k < k0 + 64; k++) {
                ulonglong2 w01 = Wd2[k * 8 + ggl * 2];
                ulonglong2 w23 = Wd2[k * 8 + ggl * 2 + 1];
                ulonglong2 hh  = H2[k * 8 + bg];
                a[0][0] = fma2(w01.x, hh.x, a[0][0]); a[0][1] = fma2(w01.x, hh.y, a[0][1]);
                a[1][0] = fma2(w01.y, hh.x, a[1][0]); a[1][1] = fma2(w01.y, hh.y, a[1][1]);
                a[2][0] = fma2(w23.x, hh.x, a[2][0]); a[2][1] = fma2(w23.x, hh.y, a[2][1]);
                a[3][0] = fma2(w23.y, hh.x, a[3][0]); a[3][1] = fma2(w23.y, hh.y, a[3][1]);
            }
#pragma unroll
            for (int i = 0; i < 4; i++) {
                ull* pr = part + (size_t)(w * 16 + ggl * 4 + i) * 17 + bg * 2;
                pr[0] = a[i][0]; pr[1] = a[i][1];
            }
        }
        __syncthreads();

        {
            const float* pf = (const float*)part;
            float g[4];
#pragma unroll
            for (int gg = 0; gg < 4; gg++) {
                float s = xgv[gg];
                if (it > 0) {
                    int r = gg * 4 + u;
#pragma unroll
                    for (int wi = 0; wi < 4; wi++)
                        s += pf[(((size_t)wi * 16 + r) * 17 + (b >> 1)) * 2 + (b & 1)];
                }
                g[gg] = s;
            }
            float iv = fsigmoid(g[0]);
            float fv = fsigmoid(g[1]);
            float gv = ftanh_fast(g[2]);
            float ov = fsigmoid(g[3]);
            c_reg = fv * c_reg + iv * gv;
            g_h[((size_t)(d * SS + t) * HH + m * 4 + u) * BB + b] = ov * ftanh_fast(c_reg);
        }
        __syncthreads();

        if (tid == 0) {
            unsigned* ap = barD + it * 4 + mygrp;
            asm volatile("red.release.gpu.global.add.u32 [%0], %1;" :: "l"(ap), "r"(1u) : "memory");
        }
    }
}

// ---------------- logits: Wtag staged in smem ----------------
__global__ __launch_bounds__(256) void logits_kernel(const float* __restrict__ Wtag,
                                                     const float* __restrict__ btag) {
    extern __shared__ float hb[];
    float* wt = hb + 512 * 32;
    int t = blockIdx.x;
    int tid = threadIdx.x;
    for (int dd = 0; dd < 2; dd++) {
        const float4* src = (const float4*)(g_h + (size_t)(dd * SS + t) * HH * BB);
        float4* dst = (float4*)(hb + (size_t)dd * HH * BB);
        for (int i = tid; i < 2048; i += 256) dst[i] = src[i];
    }
    {
        const float4* ws = (const float4*)Wtag;
        float4* wd = (float4*)wt;
        for (int i = tid; i < 2432; i += 256) wd[i] = ws[i];
    }
    __syncthreads();
    for (int o = tid; o < BB * NT; o += 256) {
        int tag = o >> 5;
        int b = o & 31;
        float acc = btag[tag];
        const float* wr = wt + tag * 512;
#pragma unroll 8
        for (int k = 0; k < 2 * HH; k++) acc += hb[k * BB + b] * wr[k];
        g_logits[((size_t)b * SS + t) * NT + tag] = acc;
    }
}

// ---------------- merged CRF forward + Viterbi, fully smem-staged ----------------
__global__ void crf_vit_kernel(const int* __restrict__ mask, const int* __restrict__ labels,
                               const float* __restrict__ trans, float* __restrict__ out) {
    extern __shared__ float smc[];
    float* tr  = smc;
    float* lg  = smc + 364;
    int*   msk = (int*)(smc + 364 + 4864);
    int*   lbl = msk + 256;
    int*   ptr_s = msk + 512;
    __shared__ float st[NT];

    int b = blockIdx.x, j = threadIdx.x;
    for (int i = j; i < NT * NT; i += 32) tr[i] = trans[i];
    {
        const float4* src = (const float4*)(g_logits + (size_t)b * SS * NT);
        float4* dst = (float4*)lg;
        for (int i = j; i < SS * NT / 4; i += 32) dst[i] = src[i];
    }
    for (int i = j; i < SS; i += 32) {
        msk[i] = mask[b * SS + i];
        lbl[i] = labels[b * SS + i];
    }
    __syncthreads();

    if (blockIdx.y == 0) {
        if (j < NT) st[j] = lg[j] + tr[TSTART * NT + j];
        __syncthreads();
        for (int t = 1; t < SS; t++) {
            int mt = msk[t];
            float nv = 0.0f;
            if (j < NT) {
                float mx = -1e30f;
#pragma unroll
                for (int i = 0; i < NT; i++) mx = fmaxf(mx, st[i] + tr[i * NT + j]);
                float sum = 0.0f;
#pragma unroll
                for (int i = 0; i < NT; i++) sum += __expf(st[i] + tr[i * NT + j] - mx);
                nv = mx + __logf(sum) + lg[t * NT + j];
            }
            __syncthreads();
            if (j < NT && mt > 0) st[j] = nv;
            __syncthreads();
        }
        if (j == 0) {
            float mx = -1e30f;
            for (int i = 0; i < NT; i++) mx = fmaxf(mx, st[i] + tr[i * NT + TSTOP]);
            float sum = 0.0f;
            for (int i = 0; i < NT; i++) sum += __expf(st[i] + tr[i * NT + TSTOP] - mx);
            float logZ = mx + __logf(sum);
            float gold = 0.0f;
            int prev = TSTART, len = 0;
            for (int t = 0; t < SS; t++) {
                int lab = lbl[t];
                if (msk[t] > 0) {
                    gold += tr[prev * NT + lab] + lg[t * NT + lab];
                    len++;
                }
                prev = lab;
            }
            int last = lbl[len - 1];
            gold += tr[last * NT + TSTOP];
            atomicAdd(out, (logZ - gold) * (1.0f / (float)BB));
        }
    } else {
        if (j < NT) st[j] = lg[j] + tr[TSTART * NT + j];
        __syncthreads();
        for (int t = 1; t < SS; t++) {
            int mt = msk[t];
            float nv = 0.0f;
            int arg = j;
            if (j < NT) {
                float best = -1e30f;
                int bi = 0;
#pragma unroll
                for (int i = 0; i < NT; i++) {
                    float v = st[i] + tr[i * NT + j];
                    if (v > best) { best = v; bi = i; }
                }
                nv = best + lg[t * NT + j];
                if (mt > 0) arg = bi;
            }
            __syncthreads();
            if (j < NT) {
                if (mt > 0) st[j] = nv;
                ptr_s[t * NT + j] = arg;
            }
            __syncthreads();
        }
        if (j == 0) {
            float best = -1e30f;
            int bl = 0;
            for (int i = 0; i < NT; i++) {
                float v = st[i] + tr[i * NT + TSTOP];
                if (v > best) { best = v; bl = i; }
            }
            int tag = bl;
            for (int t = SS - 1; t >= 1; t--) {
                out[1 + b * SS + t] = (float)(msk[t] > 0 ? tag : 0);
                tag = ptr_s[t * NT + tag];
            }
            out[1 + b * SS + 0] = (float)(msk[0] > 0 ? tag : 0);
        }
    }
}

extern "C" void kernel_launch(void* const* d_in, const int* in_sizes, int n_in,
                              void* d_out, int out_size) {
    int o = (in_sizes[4] == 1) ? 0 : -1;
    const int*   word   = (const int*)d_in[0];
    const int*   mask   = (const int*)d_in[1];
    const int*   labels = (const int*)d_in[2];
    const float* emb    = (const float*)d_in[5 + o];
    const float* WihF   = (const float*)d_in[6 + o];
    const float* WhhF   = (const float*)d_in[7 + o];
    const float* bihF   = (const float*)d_in[8 + o];
    const float* bhhF   = (const float*)d_in[9 + o];
    const float* WihB   = (const float*)d_in[10 + o];
    const float* WhhB   = (const float*)d_in[11 + o];
    const float* bihB   = (const float*)d_in[12 + o];
    const float* bhhB   = (const float*)d_in[13 + o];
    const float* Wtag   = (const float*)d_in[14 + o];
    const float* btag   = (const float*)d_in[15 + o];
    const float* trans  = (const float*)d_in[16 + o];
    float* out = (float*)d_out;

    const int lstm_smem = (4096 + 4096 + 1088) * 8;
    const int logits_smem = (512 * 32 + 19 * 512) * 4;
    const int crf_smem = (364 + 4864 + 256 + 256 + 4864) * 4;
    cudaFuncSetAttribute(lstm_kernel, cudaFuncAttributeMaxDynamicSharedMemorySize, lstm_smem);
    cudaFuncSetAttribute(logits_kernel, cudaFuncAttributeMaxDynamicSharedMemorySize, logits_smem);

    embed_kernel<<<(BB * SS * (EP / 4) + 255) / 256, 256>>>(word, mask, emb, out);
    {
        dim3 grid(BB * SS / 128, T4H / 64, 2);
        gemm_xg_kernel<<<grid, 256>>>(WihF, WihB, bihF, bhhF, bihB, bhhB);
    }
    lstm_kernel<<<128, 128, lstm_smem>>>(WhhF, WhhB);
    logits_kernel<<<SS, 256, logits_smem>>>(Wtag, btag);
    crf_vit_kernel<<<dim3(BB, 2), 32, crf_smem>>>(mask, labels, trans, out);
}